// round 5
// baseline (speedup 1.0000x reference)
#include <cuda_runtime.h>

#define BB   1024
#define TT   512
#define IN   6
#define HH   64
#define GG   256
#define RR   8
#define NTH  512
#define NCTA (BB / RR)
#define NKQ  16      // k-quads per H matvec

// hT layout: hT[kp*32 + r*2 + par]  (128B stride per k-pair -> single-line loads)
// smem offsets (floats)
#define OFF_W4HH0 0
#define OFF_W4IH1 (OFF_W4HH0 + NKQ*GG*4)   // 16384
#define OFF_W4HH1 (OFF_W4IH1 + NKQ*GG*4)   // 32768
#define OFF_W2IH0 (OFF_W4HH1 + NKQ*GG*4)   // 49152
#define OFF_B0    (OFF_W2IH0 + 1536)
#define OFF_B1    (OFF_B0 + GG)
#define OFF_GSH1  (OFF_B1 + GG)            // [g][r] 2048
#define OFF_GSHP  (OFF_GSH1 + GG*RR)       // 2048
#define OFF_HT0   (OFF_GSHP + GG*RR)       // 32*32 = 1024
#define OFF_HT1   (OFF_HT0 + 1024)
#define OFF_XT    (OFF_HT1 + 1024)         // 3*32 -> pad 128
#define SMEM_FLOATS (OFF_XT + 128)
#define SMEM_BYTES  (SMEM_FLOATS * 4)      // 229888 B

typedef unsigned long long u64;

__device__ __forceinline__ u64 ffma2(u64 a, u64 b, u64 c) {
    u64 d;
    asm("fma.rn.f32x2 %0, %1, %2, %3;" : "=l"(d) : "l"(a), "l"(b), "l"(c));
    return d;
}
__device__ __forceinline__ float hsum2(u64 a) {
    union { u64 u; float2 f; } cvt; cvt.u = a;
    return cvt.f.x + cvt.f.y;
}
__device__ __forceinline__ float fex2(float x) {
    float y; asm("ex2.approx.ftz.f32 %0, %1;" : "=f"(y) : "f"(x)); return y;
}
__device__ __forceinline__ float frcp(float x) {
    float y; asm("rcp.approx.ftz.f32 %0, %1;" : "=f"(y) : "f"(x)); return y;
}
__device__ __forceinline__ float sigmoidf_(float x) {
    return frcp(1.0f + fex2(-1.4426950408889634f * x));
}
__device__ __forceinline__ float tanhf_(float x) {
    return fmaf(2.0f, frcp(1.0f + fex2(-2.8853900817779268f * x)), -1.0f);
}

__global__ void __launch_bounds__(NTH, 1)
lstm_net_kernel(const float* __restrict__ x,
                const float* __restrict__ Wih0, const float* __restrict__ Whh0,
                const float* __restrict__ bih0, const float* __restrict__ bhh0,
                const float* __restrict__ Wih1, const float* __restrict__ Whh1,
                const float* __restrict__ bih1, const float* __restrict__ bhh1,
                const float* __restrict__ Wfc1, const float* __restrict__ bfc1,
                const float* __restrict__ Wfc2, const float* __restrict__ bfc2,
                float* __restrict__ out) {
    extern __shared__ float s[];
    float* Whh0s = s + OFF_W4HH0;
    float* Wih1s = s + OFF_W4IH1;
    float* Whh1s = s + OFF_W4HH1;
    float* Wih0s = s + OFF_W2IH0;
    float* b0s   = s + OFF_B0;
    float* b1s   = s + OFF_B1;
    float* gsh1  = s + OFF_GSH1;   // layer-1 gates (t)
    float* gshP  = s + OFF_GSHP;   // layer-0 gates (t+1)
    float* hT0   = s + OFF_HT0;
    float* hT1   = s + OFF_HT1;
    float* xT    = s + OFF_XT;

    const int tid  = threadIdx.x;
    const int lane = tid & 31;
    const int w    = tid >> 5;
    const int gl   = lane & 15;
    const int rh   = lane >> 4;            // row-half: rows rh*4 .. rh*4+3
    const int g    = w * 16 + gl;          // gate column (full k per lane)
    const int rh8  = rh * 8;               // float offset of this row-half in a kp row
    const int b0   = blockIdx.x * RR;

    // ---- Stage weights: quad layout W4[(kq*GG+g)*4 + (k&3)]
    for (int i = tid; i < HH * GG; i += NTH) {
        int gg_ = i >> 6;
        int k   = i & 63;
        int dst = ((k >> 2) * GG + gg_) * 4 + (k & 3);
        Whh0s[dst] = Whh0[i];
        Wih1s[dst] = Wih1[i];
        Whh1s[dst] = Whh1[i];
    }
    for (int i = tid; i < IN * GG; i += NTH) {
        int gg_ = i / IN;
        int k   = i - gg_ * IN;
        Wih0s[((k >> 1) * GG + gg_) * 2 + (k & 1)] = Wih0[i];
    }
    if (tid < GG) {
        b0s[tid] = bih0[tid] + bhh0[tid];
        b1s[tid] = bih1[tid] + bhh1[tid];
    }
    for (int i = tid; i < 1024; i += NTH) { hT0[i] = 0.0f; hT1[i] = 0.0f; }

    // x staging threads: (xk, xr) for tid < 48
    const int xk = tid >> 3;
    const int xr = tid & 7;
    float xreg = 0.0f;
    if (tid < IN * RR) xreg = x[(size_t)(b0 + xr) * TT * IN + xk];   // x_0

    // update role: (r = tid&7, j = tid>>3)
    const int ur = tid & 7;
    const int uj = tid >> 3;
    float c0 = 0.0f, c1 = 0.0f;

    __syncthreads();

    const float bias0 = b0s[g];
    const float bias1 = b1s[g];

    // publish x_0
    if (tid < IN * RR) xT[(xk >> 1) * 32 + xr * 2 + (xk & 1)] = xreg;
    __syncthreads();

    // ================= PROLOGUE: gates0_0 = bias0 + Wih0 @ x_0 =================
    {
        u64 accP[4] = {0ULL, 0ULL, 0ULL, 0ULL};
#pragma unroll
        for (int kp = 0; kp < 3; kp++) {
            u64 wx = *(const u64*)(Wih0s + (kp * GG + g) * 2);
            ulonglong2 A = *(const ulonglong2*)(xT + kp * 32 + rh8);
            ulonglong2 B = *(const ulonglong2*)(xT + kp * 32 + rh8 + 4);
            accP[0] = ffma2(A.x, wx, accP[0]);
            accP[1] = ffma2(A.y, wx, accP[1]);
            accP[2] = ffma2(B.x, wx, accP[2]);
            accP[3] = ffma2(B.y, wx, accP[3]);
        }
        float4 vP = make_float4(hsum2(accP[0]) + bias0, hsum2(accP[1]) + bias0,
                                hsum2(accP[2]) + bias0, hsum2(accP[3]) + bias0);
        *(float4*)(gshP + g * 8 + rh * 4) = vP;
        if (tid < IN * RR)   // load x_1
            xreg = x[(size_t)(b0 + xr) * TT * IN + 1 * IN + xk];
        __syncthreads();

        // prologue update: layer 0 only -> h0_0
        float gi = sigmoidf_(gshP[uj * 8 + ur]);
        float gf = sigmoidf_(gshP[(uj + 64) * 8 + ur]);
        float gc = tanhf_  (gshP[(uj + 128) * 8 + ur]);
        float go = sigmoidf_(gshP[(uj + 192) * 8 + ur]);
        c0 = fmaf(gf, c0, gi * gc);
        hT0[(uj >> 1) * 32 + ur * 2 + (uj & 1)] = go * tanhf_(c0);
        if (tid < IN * RR) xT[(xk >> 1) * 32 + xr * 2 + (xk & 1)] = xreg;  // publish x_1
        __syncthreads();
    }

    // ================= MAIN LOOP =================
    for (int t = 0; t < TT; t++) {
        // ---------- PHASE 1 ----------
        // acc1 = Wih1@h0_t + Whh1@h1_{t-1}    (layer-1 gates, step t)
        // accP = Whh0@h0_t + Wih0@x_{t+1}     (layer-0 gates, step t+1)
        u64 acc1[4] = {0ULL, 0ULL, 0ULL, 0ULL};
        u64 accP[4] = {0ULL, 0ULL, 0ULL, 0ULL};

#pragma unroll
        for (int kq = 0; kq < NKQ; kq++) {
            const int wbase = (kq * GG + g) * 4;
            ulonglong2 w1 = *(const ulonglong2*)(Wih1s + wbase);
            ulonglong2 wp = *(const ulonglong2*)(Whh0s + wbase);
            ulonglong2 wh = *(const ulonglong2*)(Whh1s + wbase);

            // h0, kp = 2kq (fused: serves Wih1 and Whh0)
            {
                ulonglong2 A = *(const ulonglong2*)(hT0 + (2 * kq) * 32 + rh8);
                ulonglong2 B = *(const ulonglong2*)(hT0 + (2 * kq) * 32 + rh8 + 4);
                acc1[0] = ffma2(A.x, w1.x, acc1[0]); accP[0] = ffma2(A.x, wp.x, accP[0]);
                acc1[1] = ffma2(A.y, w1.x, acc1[1]); accP[1] = ffma2(A.y, wp.x, accP[1]);
                acc1[2] = ffma2(B.x, w1.x, acc1[2]); accP[2] = ffma2(B.x, wp.x, accP[2]);
                acc1[3] = ffma2(B.y, w1.x, acc1[3]); accP[3] = ffma2(B.y, wp.x, accP[3]);
            }
            // h0, kp = 2kq+1
            {
                ulonglong2 A = *(const ulonglong2*)(hT0 + (2 * kq + 1) * 32 + rh8);
                ulonglong2 B = *(const ulonglong2*)(hT0 + (2 * kq + 1) * 32 + rh8 + 4);
                acc1[0] = ffma2(A.x, w1.y, acc1[0]); accP[0] = ffma2(A.x, wp.y, accP[0]);
                acc1[1] = ffma2(A.y, w1.y, acc1[1]); accP[1] = ffma2(A.y, wp.y, accP[1]);
                acc1[2] = ffma2(B.x, w1.y, acc1[2]); accP[2] = ffma2(B.x, wp.y, accP[2]);
                acc1[3] = ffma2(B.y, w1.y, acc1[3]); accP[3] = ffma2(B.y, wp.y, accP[3]);
            }
            // h1, kp = 2kq
            {
                ulonglong2 A = *(const ulonglong2*)(hT1 + (2 * kq) * 32 + rh8);
                ulonglong2 B = *(const ulonglong2*)(hT1 + (2 * kq) * 32 + rh8 + 4);
                acc1[0] = ffma2(A.x, wh.x, acc1[0]);
                acc1[1] = ffma2(A.y, wh.x, acc1[1]);
                acc1[2] = ffma2(B.x, wh.x, acc1[2]);
                acc1[3] = ffma2(B.y, wh.x, acc1[3]);
            }
            // h1, kp = 2kq+1
            {
                ulonglong2 A = *(const ulonglong2*)(hT1 + (2 * kq + 1) * 32 + rh8);
                ulonglong2 B = *(const ulonglong2*)(hT1 + (2 * kq + 1) * 32 + rh8 + 4);
                acc1[0] = ffma2(A.x, wh.y, acc1[0]);
                acc1[1] = ffma2(A.y, wh.y, acc1[1]);
                acc1[2] = ffma2(B.x, wh.y, acc1[2]);
                acc1[3] = ffma2(B.y, wh.y, acc1[3]);
            }
        }
        // x part: accP += Wih0 @ x_{t+1}
#pragma unroll
        for (int kp = 0; kp < 3; kp++) {
            u64 wx = *(const u64*)(Wih0s + (kp * GG + g) * 2);
            ulonglong2 A = *(const ulonglong2*)(xT + kp * 32 + rh8);
            ulonglong2 B = *(const ulonglong2*)(xT + kp * 32 + rh8 + 4);
            accP[0] = ffma2(A.x, wx, accP[0]);
            accP[1] = ffma2(A.y, wx, accP[1]);
            accP[2] = ffma2(B.x, wx, accP[2]);
            accP[3] = ffma2(B.y, wx, accP[3]);
        }
        // prefetch x_{t+2}
        if (tid < IN * RR && t + 2 < TT)
            xreg = x[(size_t)(b0 + xr) * TT * IN + (size_t)(t + 2) * IN + xk];

        // store gates (complete sums, no combining needed)
        *(float4*)(gsh1 + g * 8 + rh * 4) =
            make_float4(hsum2(acc1[0]) + bias1, hsum2(acc1[1]) + bias1,
                        hsum2(acc1[2]) + bias1, hsum2(acc1[3]) + bias1);
        *(float4*)(gshP + g * 8 + rh * 4) =
            make_float4(hsum2(accP[0]) + bias0, hsum2(accP[1]) + bias0,
                        hsum2(accP[2]) + bias0, hsum2(accP[3]) + bias0);
        __syncthreads();

        // ---------- PHASE 2: both cell updates ----------
        {
            float gi = sigmoidf_(gsh1[uj * 8 + ur]);
            float gf = sigmoidf_(gsh1[(uj + 64) * 8 + ur]);
            float gc = tanhf_  (gsh1[(uj + 128) * 8 + ur]);
            float go = sigmoidf_(gsh1[(uj + 192) * 8 + ur]);
            c1 = fmaf(gf, c1, gi * gc);
            hT1[(uj >> 1) * 32 + ur * 2 + (uj & 1)] = go * tanhf_(c1);   // h1_t
        }
        {
            float gi = sigmoidf_(gshP[uj * 8 + ur]);
            float gf = sigmoidf_(gshP[(uj + 64) * 8 + ur]);
            float gc = tanhf_  (gshP[(uj + 128) * 8 + ur]);
            float go = sigmoidf_(gshP[(uj + 192) * 8 + ur]);
            c0 = fmaf(gf, c0, gi * gc);
            hT0[(uj >> 1) * 32 + ur * 2 + (uj & 1)] = go * tanhf_(c0);   // h0_{t+1}
        }
        if (tid < IN * RR && t + 2 < TT)
            xT[(xk >> 1) * 32 + xr * 2 + (xk & 1)] = xreg;               // publish x_{t+2}
        __syncthreads();
    }

    // ================= FC head on h1_{T-1} =================
    if (tid < 256) {
        const int row = tid >> 5;
        const int m   = tid & 31;
        float acc2 = bfc1[m];
#pragma unroll 8
        for (int k = 0; k < HH; k++)
            acc2 = fmaf(hT1[(k >> 1) * 32 + row * 2 + (k & 1)],
                        Wfc1[m * HH + k], acc2);
        acc2 = fmaxf(acc2, 0.0f) * Wfc2[m];
#pragma unroll
        for (int off = 16; off > 0; off >>= 1)
            acc2 += __shfl_down_sync(0xffffffffu, acc2, off);
        if (m == 0)
            out[b0 + row] = acc2 + bfc2[0];
    }
}

extern "C" void kernel_launch(void* const* d_in, const int* in_sizes, int n_in,
                              void* d_out, int out_size) {
    const float* x    = (const float*)d_in[0];
    const float* Wih0 = (const float*)d_in[1];
    const float* Whh0 = (const float*)d_in[2];
    const float* bih0 = (const float*)d_in[3];
    const float* bhh0 = (const float*)d_in[4];
    const float* Wih1 = (const float*)d_in[5];
    const float* Whh1 = (const float*)d_in[6];
    const float* bih1 = (const float*)d_in[7];
    const float* bhh1 = (const float*)d_in[8];
    const float* Wfc1 = (const float*)d_in[9];
    const float* bfc1 = (const float*)d_in[10];
    const float* Wfc2 = (const float*)d_in[11];
    const float* bfc2 = (const float*)d_in[12];
    float* out = (float*)d_out;

    cudaFuncSetAttribute(lstm_net_kernel,
                         cudaFuncAttributeMaxDynamicSharedMemorySize, SMEM_BYTES);
    lstm_net_kernel<<<NCTA, NTH, SMEM_BYTES>>>(
        x, Wih0, Whh0, bih0, bhh0, Wih1, Whh1, bih1, bhh1,
        Wfc1, bfc1, Wfc2, bfc2, out);
}